// round 16
// baseline (speedup 1.0000x reference)
#include <cuda_runtime.h>
#include <cuda_fp16.h>
#include <math.h>
#include <stdint.h>

#define NN 207
#define BB 32
#define TT 12
#define CC 2
#define HORZ 12
#define DID 64
#define HH 128
#define CONCATN 2560          // DID + TT + NN*TT
#define MROWS (BB*NN*CC)      // 13248 = 138*96
#define MPAD 13248
#define BNCNT (BB*NN)         // 6624
#define GMX 138
#define EPSILON_V 10.0f
#define EPS_V 1e-8f
#define HIN_B (CC*TT*NN)      // 4968, per-batch h_in block, layout [c][t][src]
#define NGRP 9                // nodes per build_hist CTA (23*9 = 207)
#define TG_NB 8               // bn per timegate CTA (828 CTAs)

// ---------------- scratch (device globals; no allocation) ----------------
__device__ __half g_Xh[(size_t)MPAD * CONCATN]; // fp16 X (~68MB)
__device__ float g_H2[MPAD * HH];               // fc2 output (back-GEMM input, fp32)
__device__ float g_F[MPAD * HORZ];
__device__ float g_hin[BB * HIN_B];             // [b][c][t][src]
__device__ float g_level[BNCNT * CC];
__device__ float g_tgf[BNCNT * HORZ];
__device__ float g_dp[NN * NN];
// transposed weights (N x K, K-major), fp16
__device__ __half g_W0t[3 * HH * CONCATN];
__device__ __half g_Wfct[3 * 2 * HH * HH];
__device__ __half g_Wbt[3 * CONCATN * HH];

// ---------------- helpers ----------------
__device__ __forceinline__ uint32_t smem_u32(const void* p) {
    uint32_t a;
    asm("{ .reg .u64 t; cvta.to.shared.u64 t, %1; cvt.u32.u64 %0, t; }" : "=r"(a) : "l"(p));
    return a;
}
__device__ __forceinline__ uint32_t pack_f16x2(float lo, float hi) {
    uint32_t r;
    asm("cvt.rn.f16x2.f32 %0, %1, %2;" : "=r"(r) : "f"(hi), "f"(lo));
    return r;
}
__device__ __forceinline__ __half2 h2_from(float a, float b) {
    return __floats2half2_rn(a, b);
}
#define CP_ASYNC16(s, g) asm volatile("cp.async.cg.shared.global [%0], [%1], 16;" :: "r"(s), "l"(g))
#define CP_COMMIT()      asm volatile("cp.async.commit_group;" ::: "memory")
#define CP_WAIT(n)       asm volatile("cp.async.wait_group %0;" :: "n"(n) : "memory")

__device__ __forceinline__ void mma_f16(float* d, const uint32_t* a, const uint32_t* b) {
    asm volatile("mma.sync.aligned.m16n8k16.row.col.f32.f16.f16.f32 "
                 "{%0,%1,%2,%3}, {%4,%5,%6,%7}, {%8,%9}, {%0,%1,%2,%3};"
                 : "+f"(d[0]), "+f"(d[1]), "+f"(d[2]), "+f"(d[3])
                 : "r"(a[0]), "r"(a[1]), "r"(a[2]), "r"(a[3]), "r"(b[0]), "r"(b[1]));
}

// ---------------- time gates + h_in + level (weights staged in smem, 8 bn/CTA) ----------------
__global__ void __launch_bounds__(256) timegate_kernel(
        const float* __restrict__ hist, const float* __restrict__ tod,
        const float* __restrict__ emb,
        const float* __restrict__ w1, const float* __restrict__ b1,
        const float* __restrict__ w2, const float* __restrict__ b2,
        const float* __restrict__ w3, const float* __restrict__ b3) {
    __shared__ float sw1[(DID + TT) * HH];   // 38912 B
    __shared__ float sw2[HH * HORZ];         // 6144 B
    __shared__ float sw3[HH * TT];           // 6144 B
    __shared__ float sb1[HH];
    __shared__ float sb23[2 * HORZ];
    __shared__ float sin_[2][DID + TT];
    __shared__ float stg[2][HH];
    __shared__ float stgb[2][TT];
    __shared__ float shin[2][TT * CC];
    int tid = threadIdx.x;                   // 256
    for (int i = tid; i < (DID + TT) * HH; i += 256) sw1[i] = w1[i];
    for (int i = tid; i < HH * HORZ; i += 256) { sw2[i] = w2[i]; sw3[i] = w3[i]; }
    if (tid < HH) sb1[tid] = b1[tid];
    else if (tid < HH + HORZ) sb23[tid - HH] = b2[tid - HH];
    else if (tid < HH + 2 * HORZ) sb23[tid - HH] = b3[tid - HH - HORZ];
    __syncthreads();

    int bn_base = blockIdx.x * TG_NB;
    const int half = tid >> 7, t = tid & 127;
#pragma unroll 1
    for (int p = 0; p < TG_NB; p += 2) {
        int bn = bn_base + p + half;
        int b = bn / NN, n = bn - b * NN;
        if (t < DID) sin_[half][t] = emb[n * DID + t];
        else if (t < DID + TT) sin_[half][t] = tod[bn * TT + (t - DID)];
        __syncthreads();
        float acc = sb1[t];
#pragma unroll 4
        for (int i = 0; i < DID + TT; i++) acc += sin_[half][i] * sw1[i * HH + t];
        stg[half][t] = fmaxf(acc, 0.f);
        __syncthreads();
        if (t < HORZ) {
            float a2 = sb23[t], a3 = sb23[HORZ + t];
#pragma unroll 8
            for (int h = 0; h < HH; h++) {
                float v = stg[half][h];
                a2 += v * sw2[h * HORZ + t];
                a3 += v * sw3[h * TT + t];
            }
            g_tgf[bn * HORZ + t] = a2;
            stgb[half][t] = a3;
        }
        __syncthreads();
        if (t < TT * CC) {
            int tt = t >> 1, c = t & 1;
            float hv = hist[((size_t)bn * TT + tt) * CC + c] / (1.f + stgb[half][tt]);
            shin[half][t] = hv;
            g_hin[b * HIN_B + (c * TT + tt) * NN + n] = hv;
        }
        __syncthreads();
        if (t < CC) {
            float mx = -1e30f;
#pragma unroll
            for (int tt = 0; tt < TT; tt++) mx = fmaxf(mx, shin[half][tt * CC + t]);
            g_level[bn * CC + t] = mx;
        }
        __syncthreads();
    }
}

// ---------------- pairwise affinities ----------------
__global__ void dp_kernel(const float* __restrict__ emb) {
    int idx = blockIdx.x * blockDim.x + threadIdx.x;
    if (idx >= NN * NN) return;
    int i = idx / NN, j = idx % NN;
    float s = 0.f;
#pragma unroll 8
    for (int k = 0; k < DID; k++) s += emb[i * DID + k] * emb[j * DID + k];
    g_dp[idx] = expf(EPSILON_V * s);
}

// ---------------- build X: one CTA per (batch, 9-node group), dp double-buffered ----------------
__global__ void build_hist_kernel(const float* __restrict__ emb) {
    int b = blockIdx.x;       // 0..31
    int grp = blockIdx.y;     // 0..22
    __shared__ __align__(16) __half sout[CC * CONCATN];  // 10240 B
    __shared__ float sh[HIN_B];              // [c][t][src], 19872 B
    __shared__ float sdp[2][NN];
    __shared__ float slvl[2][CC];
    int tid = threadIdx.x;                   // 256

    const float4* hin4 = reinterpret_cast<const float4*>(&g_hin[b * HIN_B]);
    float4* sh4 = reinterpret_cast<float4*>(sh);
    for (int i = tid; i < HIN_B / 4; i += 256) sh4[i] = hin4[i];
    {
        int n0 = grp * NGRP;
        if (tid < NN) sdp[0][tid] = g_dp[n0 * NN + tid];
        if (tid >= 254) slvl[0][tid - 254] = g_level[(b * NN + n0) * CC + (tid - 254)];
    }
    __syncthreads();

    for (int nn = 0; nn < NGRP; nn++) {
        int cur = nn & 1;
        int n = grp * NGRP + nn;
        int bn = b * NN + n;
        if (nn + 1 < NGRP) {
            int n1 = n + 1;
            if (tid < NN) sdp[cur ^ 1][tid] = g_dp[n1 * NN + tid];
            if (tid >= 254) slvl[cur ^ 1][tid - 254] = g_level[(bn + 1) * CC + (tid - 254)];
        }
        float lv[2] = {slvl[cur][0], slvl[cur][1]};
        float rl[2] = {1.f / (lv[0] + EPS_V), 1.f / (lv[1] + EPS_V)};

        for (int pair = tid; pair < 2 * NN; pair += 256) {
            int c = (pair >= NN) ? 1 : 0;
            int src = pair - NN * c;
            float d = sdp[cur][src];
            float l = lv[c], r = rl[c];
            float v[12];
#pragma unroll
            for (int t = 0; t < 12; t++) {
                float a = sh[(c * TT + t) * NN + src] * d;
                v[t] = fmaxf((a - l) * r, 0.f);
            }
            __half2* dst = reinterpret_cast<__half2*>(&sout[c * CONCATN + 12 + src * 12]);
#pragma unroll
            for (int q = 0; q < 6; q++) dst[q] = h2_from(v[2 * q], v[2 * q + 1]);
        }
        if (tid < 24) {
            int c = tid >= 12 ? 1 : 0;
            int t = tid - 12 * c;
            sout[c * CONCATN + t] = __float2half_rn(sh[(c * TT + t) * NN + n] * rl[c]);
        }
        if (tid < 128) {
            int c = tid >> 6, d = tid & 63;
            sout[c * CONCATN + (TT + NN * TT) + d] = __float2half_rn(emb[n * DID + d]);
        }
        __syncthreads();
        uint4* xb4 = reinterpret_cast<uint4*>(&g_Xh[(size_t)bn * CC * CONCATN]);
        const uint4* s4 = reinterpret_cast<const uint4*>(sout);
#pragma unroll
        for (int p = 0; p < 3; p++) {
            int i = tid + (p << 8);
            if (i < 640) xb4[i] = s4[i];
        }
        __syncthreads();
    }
}

// ---------------- batched weight transpose -> fp16 (N x K) ----------------
__global__ void transpose_all_kernel(const float* __restrict__ fc0_w,
                                     const float* __restrict__ fc_w,
                                     const float* __restrict__ back_w) {
    __shared__ float t[32][33];
    int idx = blockIdx.x;
    int blk = idx / 672;
    int r = idx % 672;
    const float* in;
    __half* out;
    int K, N, kb, nb;
    if (r < 320) {
        in = fc0_w + (size_t)blk * CONCATN * HH;
        out = g_W0t + (size_t)blk * HH * CONCATN;
        K = CONCATN; N = HH; kb = (r % 80) * 32; nb = (r / 80) * 32;
    } else if (r < 336) {
        r -= 320;
        in = fc_w + ((size_t)blk * 2 + 0) * HH * HH;
        out = g_Wfct + ((size_t)blk * 2 + 0) * HH * HH;
        K = HH; N = HH; kb = (r % 4) * 32; nb = (r / 4) * 32;
    } else if (r < 352) {
        r -= 336;
        in = fc_w + ((size_t)blk * 2 + 1) * HH * HH;
        out = g_Wfct + ((size_t)blk * 2 + 1) * HH * HH;
        K = HH; N = HH; kb = (r % 4) * 32; nb = (r / 4) * 32;
    } else {
        r -= 352;
        in = back_w + (size_t)blk * HH * CONCATN;
        out = g_Wbt + (size_t)blk * CONCATN * HH;
        K = HH; N = CONCATN; kb = (r % 4) * 32; nb = (r / 4) * 32;
    }
    int x = threadIdx.x, y = threadIdx.y;  // 32 x 8
#pragma unroll
    for (int rr = 0; rr < 32; rr += 8)
        t[y + rr][x] = in[(size_t)(kb + y + rr) * N + nb + x];
    __syncthreads();
#pragma unroll
    for (int rr = 0; rr < 32; rr += 8)
        out[(size_t)(nb + y + rr) * K + kb + x] = __float2half_rn(t[x][y + rr]);
}

// ---------------- shared tiling constants ----------------
#define G_BM 96
#define G_BN 128
#define SB_STR 40                        // halves per B smem row
#define B_STG_B (G_BN * SB_STR * 2)      // 10240 bytes

// ===== block_mlp: fp16 A (X) =====
#define MB_ASTG (G_BM * 40 * 2)          // 7680 bytes (A fp16, stride 40 halves)
#define MB_STG (MB_ASTG + B_STG_B)       // 17920
#define WF_OFF (3 * MB_STG)              // 53760
#define WFMAT 40960
#define WFCH 10240
#define HSTR 136
#define H_BYTES (G_BM * HSTR * 2)        // 26112
#define H0_OFF (WF_OFF + 2 * WFMAT)      // 135680
#define H1_OFF (H0_OFF + H_BYTES)        // 161792
#define FW_OFF (H1_OFF + H_BYTES)        // 187904
#define BLK_SMEM (FW_OFF + 6144)         // 194048

// ===== back gemm: fp32 A (H2), 2-stage, X staging =====
#define BA_STR 40                        // floats per A smem row
#define BA_STG_B (G_BM * BA_STR * 4)     // 15360
#define BSTG_B (BA_STG_B + B_STG_B)      // 25600
#define XS_OFF (2 * BSTG_B)              // 51200
#define XS_BYTES (G_BM * HSTR * 2)       // 26112 (stride 136 halves)
#define OS_OFF (XS_OFF + XS_BYTES)       // 77312
#define OS_BYTES 24576                   // 24 bn x 256 floats
#define BACK_SMEM (OS_OFF + OS_BYTES)    // 101888

// ---------------- fused block kernel: fc0 -> fc1 -> fc2 -> fore ----------------
__global__ void __launch_bounds__(256) block_mlp_kernel(
        const __half* __restrict__ Xh, const __half* __restrict__ W0t,
        const float* __restrict__ b0,
        const __half* __restrict__ Wf, const float* __restrict__ fcb,
        const float* __restrict__ fore_w, const float* __restrict__ fore_b,
        float* __restrict__ H2out, float* __restrict__ Fbuf,
        float* __restrict__ outF, int blk) {
    extern __shared__ char smc[];
    const int tid = threadIdx.x;
    const int wid = tid >> 5, lid = tid & 31;
    const int wm = wid >> 2, wn = wid & 3;
    const int g = lid >> 2, t = lid & 3;
    const int m0 = blockIdx.x * G_BM;

    const __half* gA = Xh + (size_t)m0 * CONCATN;
    const __half* gB = W0t;
    const uint32_t sm_u = smem_u32(smc);
    const int nch = CONCATN >> 5;              // 80

    // preload Wf1/Wf2 + fore_w
#pragma unroll
    for (int p = 0; p < 16; p++) {
        int idx = tid + (p << 8);
        int w = idx >> 11;
        int rem = idx & 2047;
        int ch = rem >> 9;
        int r2 = rem & 511;
        int row = r2 >> 2;
        int kh = (r2 & 3) << 3;
        CP_ASYNC16(sm_u + WF_OFF + w * WFMAT + ch * WFCH + (row * 40 + kh) * 2,
                   Wf + (size_t)w * HH * HH + row * HH + ch * 32 + kh);
    }
#pragma unroll
    for (int p = 0; p < 2; p++) {
        int idx = tid + (p << 8);
        if (idx < 384)
            CP_ASYNC16(sm_u + FW_OFF + idx * 16, fore_w + idx * 4);
    }
    CP_COMMIT();

    auto load_tiles = [&](int k0, int st) {
        uint32_t base = sm_u + st * MB_STG;
        {
            int idx = tid;
            int row = idx >> 2, kh = (idx & 3) << 3;
            CP_ASYNC16(base + (row * 40 + kh) * 2, gA + (size_t)row * CONCATN + k0 + kh);
        }
        if (tid < 128) {
            int idx = tid + 256;
            int row = idx >> 2, kh = (idx & 3) << 3;
            CP_ASYNC16(base + (row * 40 + kh) * 2, gA + (size_t)row * CONCATN + k0 + kh);
        }
        uint32_t baseB = base + MB_ASTG;
#pragma unroll
        for (int p = 0; p < 2; p++) {
            int idx = tid + (p << 8);
            int row = idx >> 2, kh = (idx & 3) << 3;
            CP_ASYNC16(baseB + (row * SB_STR + kh) * 2, gB + (size_t)row * CONCATN + k0 + kh);
        }
        CP_COMMIT();
    };

    float acc[3][4][4];
#pragma unroll
    for (int mf = 0; mf < 3; mf++)
#pragma unroll
        for (int nf = 0; nf < 4; nf++)
#pragma unroll
            for (int q = 0; q < 4; q++) acc[mf][nf][q] = 0.f;

    // ========== stage 1: fc0 (K=2560, 3-stage) ==========
    load_tiles(0, 0);
    load_tiles(32, 1);

    for (int ch = 0; ch < nch; ch++) {
        int st = ch % 3;
        if (ch + 2 < nch) {
            load_tiles((ch + 2) << 5, (ch + 2) % 3);
            CP_WAIT(2);
        } else if (ch + 1 < nch) {
            CP_WAIT(1);
        } else {
            CP_WAIT(0);
        }
        __syncthreads();

        const uint32_t* sA = reinterpret_cast<const uint32_t*>(smc + st * MB_STG);
        const uint32_t* sB = reinterpret_cast<const uint32_t*>(smc + st * MB_STG + MB_ASTG);
#pragma unroll
        for (int ks = 0; ks < 2; ks++) {
            uint32_t af[3][4];
#pragma unroll
            for (int mf = 0; mf < 3; mf++) {
                int r = wm * 48 + mf * 16 + g;
                int base = r * 20 + ks * 8 + t;
                af[mf][0] = sA[base];
                af[mf][1] = sA[base + 160];
                af[mf][2] = sA[base + 4];
                af[mf][3] = sA[base + 164];
            }
            uint32_t bf[4][2];
#pragma unroll
            for (int nf = 0; nf < 4; nf++) {
                int n = wn * 32 + nf * 8 + g;
                int base = n * 20 + ks * 8 + t;
                bf[nf][0] = sB[base];
                bf[nf][1] = sB[base + 4];
            }
#pragma unroll
            for (int mf = 0; mf < 3; mf++)
#pragma unroll
                for (int nf = 0; nf < 4; nf++)
                    mma_f16(acc[mf][nf], af[mf], bf[nf]);
        }
        __syncthreads();
    }

    __half* sH0h = reinterpret_cast<__half*>(smc + H0_OFF);
    __half* sH1h = reinterpret_cast<__half*>(smc + H1_OFF);
#pragma unroll
    for (int mf = 0; mf < 3; mf++)
#pragma unroll
        for (int nf = 0; nf < 4; nf++) {
            int row = wm * 48 + mf * 16 + g;
            int col = wn * 32 + nf * 8 + 2 * t;
            float2 bv = *reinterpret_cast<const float2*>(&b0[col]);
            *reinterpret_cast<__half2*>(&sH0h[row * HSTR + col]) =
                h2_from(fmaxf(acc[mf][nf][0] + bv.x, 0.f), fmaxf(acc[mf][nf][1] + bv.y, 0.f));
            *reinterpret_cast<__half2*>(&sH0h[(row + 8) * HSTR + col]) =
                h2_from(fmaxf(acc[mf][nf][2] + bv.x, 0.f), fmaxf(acc[mf][nf][3] + bv.y, 0.f));
        }
    __syncthreads();

    // ========== stages 2/3: fc1, fc2 from smem ==========
#pragma unroll 1
    for (int stage = 0; stage < 2; stage++) {
        const uint32_t* sAH = reinterpret_cast<const uint32_t*>(stage == 0 ? sH0h : sH1h);
        const float* bias = fcb + stage * HH;
#pragma unroll
        for (int mf = 0; mf < 3; mf++)
#pragma unroll
            for (int nf = 0; nf < 4; nf++)
#pragma unroll
                for (int q = 0; q < 4; q++) acc[mf][nf][q] = 0.f;

#pragma unroll
        for (int ch = 0; ch < 4; ch++) {
            const uint32_t* W32 = reinterpret_cast<const uint32_t*>(
                smc + WF_OFF + stage * WFMAT + ch * WFCH);
#pragma unroll
            for (int ks = 0; ks < 2; ks++) {
                uint32_t af[3][4];
#pragma unroll
                for (int mf = 0; mf < 3; mf++) {
                    int r = wm * 48 + mf * 16 + g;
                    int base = r * (HSTR / 2) + ch * 16 + ks * 8 + t;
                    af[mf][0] = sAH[base];
                    af[mf][1] = sAH[base + 8 * (HSTR / 2)];
                    af[mf][2] = sAH[base + 4];
                    af[mf][3] = sAH[base + 8 * (HSTR / 2) + 4];
                }
                uint32_t bf[4][2];
#pragma unroll
                for (int nf = 0; nf < 4; nf++) {
                    int n = wn * 32 + nf * 8 + g;
                    int base = n * (SB_STR / 2) + ks * 8 + t;
                    bf[nf][0] = W32[base];
                    bf[nf][1] = W32[base + 4];
                }
#pragma unroll
                for (int mf = 0; mf < 3; mf++)
#pragma unroll
                    for (int nf = 0; nf < 4; nf++)
                        mma_f16(acc[mf][nf], af[mf], bf[nf]);
            }
        }

        if (stage == 0) {
#pragma unroll
            for (int mf = 0; mf < 3; mf++)
#pragma unroll
                for (int nf = 0; nf < 4; nf++) {
                    int row = wm * 48 + mf * 16 + g;
                    int col = wn * 32 + nf * 8 + 2 * t;
                    float2 bv = *reinterpret_cast<const float2*>(&bias[col]);
                    *reinterpret_cast<__half2*>(&sH1h[row * HSTR + col]) =
                        h2_from(fmaxf(acc[mf][nf][0] + bv.x, 0.f), fmaxf(acc[mf][nf][1] + bv.y, 0.f));
                    *reinterpret_cast<__half2*>(&sH1h[(row + 8) * HSTR + col]) =
                        h2_from(fmaxf(acc[mf][nf][2] + bv.x, 0.f), fmaxf(acc[mf][nf][3] + bv.y, 0.f));
                }
        } else {
#pragma unroll
            for (int mf = 0; mf < 3; mf++)
#pragma unroll
                for (int nf = 0; nf < 4; nf++) {
                    int row = wm * 48 + mf * 16 + g;
                    int col = wn * 32 + nf * 8 + 2 * t;
                    float2 bv = *reinterpret_cast<const float2*>(&bias[col]);
                    float v0 = fmaxf(acc[mf][nf][0] + bv.x, 0.f);
                    float v1 = fmaxf(acc[mf][nf][1] + bv.y, 0.f);
                    float v2 = fmaxf(acc[mf][nf][2] + bv.x, 0.f);
                    float v3 = fmaxf(acc[mf][nf][3] + bv.y, 0.f);
                    float2 r0; r0.x = v0; r0.y = v1;
                    float2 r1; r1.x = v2; r1.y = v3;
                    *reinterpret_cast<float2*>(&H2out[(size_t)(m0 + row) * HH + col]) = r0;
                    *reinterpret_cast<float2*>(&H2out[(size_t)(m0 + row + 8) * HH + col]) = r1;
                    *reinterpret_cast<__half2*>(&sH0h[row * HSTR + col]) = h2_from(v0, v1);
                    *reinterpret_cast<__half2*>(&sH0h[(row + 8) * HSTR + col]) = h2_from(v2, v3);
                }
        }
        __syncthreads();
    }

    // ========== stage 4: fore (SIMT, N=12) ==========
    const float* sFW = reinterpret_cast<const float*>(smc + FW_OFF);
    for (int o = tid; o < G_BM * HORZ; o += 256) {
        int row = o / HORZ, col = o - row * HORZ;
        float a = __ldg(&fore_b[col]);
#pragma unroll 16
        for (int k = 0; k < HH; k++)
            a += __half2float(sH0h[row * HSTR + k]) * sFW[k * HORZ + col];
        int gr = m0 + row;
        if (blk == 0) {
            Fbuf[gr * HORZ + col] = a;
        } else if (blk == 1) {
            Fbuf[gr * HORZ + col] += a;
        } else {
            float tot = Fbuf[gr * HORZ + col] + a;
            int bn = gr >> 1, c = gr & 1;
            tot *= g_level[bn * CC + c] * (1.f + g_tgf[bn * HORZ + col]);
            outF[bn * (HORZ * CC) + col * CC + c] = tot;
        }
    }
}

// ---------------- back GEMM (fp32 A=H2, fp16 X, staged epilogues) ----------------
template <int EPI>
__global__ void __launch_bounds__(256) gemm_back_kernel(
        const float* __restrict__ A, const __half* __restrict__ Bt,
        const float* __restrict__ bias, __half* __restrict__ Xh,
        float* __restrict__ outp) {
    extern __shared__ char smc[];
    const int tid = threadIdx.x;
    const int wid = tid >> 5, lid = tid & 31;
    const int wm = wid >> 2, wn = wid & 3;
    const int g = lid >> 2, t = lid & 3;
    const int m0 = blockIdx.x * G_BM, n0 = blockIdx.y * G_BN;
    const int K = HH;
    const int nch = 4;

    const float* gA = A + (size_t)m0 * K;
    const __half* gB = Bt + (size_t)n0 * K;
    __half* gX = Xh + (size_t)m0 * CONCATN + n0;
    const uint32_t sm_u = smem_u32(smc);

    auto issue_tile = [&](int k0, int st) {
        uint32_t base = sm_u + st * BSTG_B;
#pragma unroll
        for (int p = 0; p < 3; p++) {
            int idx = tid + (p << 8);
            int row = idx >> 3, kc = (idx & 7) << 2;
            CP_ASYNC16(base + (row * BA_STR + kc) * 4, gA + (size_t)row * K + k0 + kc);
        }
        uint32_t baseB = base + BA_STG_B;
#pragma unroll
        for (int p = 0; p < 2; p++) {
            int idx = tid + (p << 8);
            int row = idx >> 2, kh = (idx & 3) << 3;
            CP_ASYNC16(baseB + (row * SB_STR + kh) * 2, gB + (size_t)row * K + k0 + kh);
        }
    };
#pragma unroll
    for (int p = 0; p < 6; p++) {
        int idx = tid + (p << 8);
        int row = idx >> 4, seg = idx & 15;
        CP_ASYNC16(sm_u + XS_OFF + row * (HSTR * 2) + seg * 16,
                   gX + (size_t)row * CONCATN + seg * 8);
    }
    issue_tile(0, 0);
    CP_COMMIT();
    issue_tile(32, 1);
    CP_COMMIT();

    float acc[3][4][4];
#pragma unroll
    for (int mf = 0; mf < 3; mf++)
#pragma unroll
        for (int nf = 0; nf < 4; nf++)
#pragma unroll
            for (int q = 0; q < 4; q++) acc[mf][nf][q] = 0.f;

    for (int ch = 0; ch < nch; ch++) {
        int st = ch & 1;
        if (ch + 1 < nch) CP_WAIT(1);
        else CP_WAIT(0);
        __syncthreads();

        const float* sA = reinterpret_cast<const float*>(smc + st * BSTG_B);
        const uint32_t* sB = reinterpret_cast<const uint32_t*>(smc + st * BSTG_B + BA_STG_B);
#pragma unroll
        for (int ks = 0; ks < 2; ks++) {
            int kb = ks << 4;
            uint32_t af[3][4];
#pragma unroll
            for (int mf = 0; mf < 3; mf++) {
                int r = wm * 48 + mf * 16 + g;
                float2 f0 = *reinterpret_cast<const float2*>(&sA[r * BA_STR + kb + 2 * t]);
                float2 f1 = *reinterpret_cast<const float2*>(&sA[(r + 8) * BA_STR + kb + 2 * t]);
                float2 f2 = *reinterpret_cast<const float2*>(&sA[r * BA_STR + kb + 8 + 2 * t]);
                float2 f3 = *reinterpret_cast<const float2*>(&sA[(r + 8) * BA_STR + kb + 8 + 2 * t]);
                af[mf][0] = pack_f16x2(f0.x, f0.y);
                af[mf][1] = pack_f16x2(f1.x, f1.y);
                af[mf][2] = pack_f16x2(f2.x, f2.y);
                af[mf][3] = pack_f16x2(f3.x, f3.y);
            }
            uint32_t bf[4][2];
#pragma unroll
            for (int nf = 0; nf < 4; nf++) {
                int n = wn * 32 + nf * 8 + g;
                int base = n * (SB_STR / 2) + ks * 8 + t;
                bf[nf][0] = sB[base];
                bf[nf][1] = sB[base + 4];
            }
#pragma unroll
            for (int mf = 0; mf < 3; mf++)
#pragma unroll
                for (int nf = 0; nf < 4; nf++)
                    mma_f16(acc[mf][nf], af[mf], bf[nf]);
        }
        __syncthreads();
        if (ch + 2 < nch) {
            issue_tile((ch + 2) << 5, st);
            CP_COMMIT();
        }
    }

    __half* XS = reinterpret_cast<__half*>(smc + XS_OFF);
    if (EPI == 1) {
#pragma unroll
        for (int mf = 0; mf < 3; mf++)
#pragma unroll
            for (int nf = 0; nf < 4; nf++) {
                int row = wm * 48 + mf * 16 + g;
                int col = wn * 32 + nf * 8 + 2 * t;
                float2 bv = *reinterpret_cast<const float2*>(&bias[n0 + col]);
                float2 o0 = __half22float2(*reinterpret_cast<const __half2*>(&XS[row * HSTR + col]));
                float2 o1 = __half22float2(*reinterpret_cast<const __half2*>(&XS[(row + 8) * HSTR + col]));
                *reinterpret_cast<__half2*>(&XS[row * HSTR + col]) =
                    h2_from(fmaxf(o0.x - (acc[mf][nf][0] + bv.x), 0.f),
                            fmaxf(o0.y - (acc[mf][nf][1] + bv.y), 0.f));
                *reinterpret_cast<__half2*>(&XS[(row + 8) * HSTR + col]) =
                    h2_from(fmaxf(o1.x - (acc[mf][nf][2] + bv.x), 0.f),
                            fmaxf(o1.y - (acc[mf][nf][3] + bv.y), 0.f));
            }
        __syncthreads();
#pragma unroll
        for (int p = 0; p < 6; p++) {
            int idx = tid + (p << 8);
            int row = idx >> 4, seg = idx & 15;
            *reinterpret_cast<uint4*>(gX + (size_t)row * CONCATN + seg * 8) =
                *reinterpret_cast<const uint4*>(&XS[row * HSTR + seg * 8]);
        }
    } else {
        float* OS = reinterpret_cast<float*>(smc + OS_OFF);
        const int bn0 = m0 >> 1;
#pragma unroll 1
        for (int pass = 0; pass < 2; pass++) {
            if (wm == pass) {
#pragma unroll
                for (int mf = 0; mf < 3; mf++)
#pragma unroll
                    for (int nf = 0; nf < 4; nf++) {
                        int row = wm * 48 + mf * 16 + g;
                        int col = wn * 32 + nf * 8 + 2 * t;
                        float2 bv = *reinterpret_cast<const float2*>(&bias[n0 + col]);
                        float2 o0 = __half22float2(*reinterpret_cast<const __half2*>(&XS[row * HSTR + col]));
                        float2 o1 = __half22float2(*reinterpret_cast<const __half2*>(&XS[(row + 8) * HSTR + col]));
                        int b0i = ((row >> 1) - pass * 24) * 256 + col * 2 + (row & 1);
                        int b1i = (((row + 8) >> 1) - pass * 24) * 256 + col * 2 + (row & 1);
                        OS[b0i] = fmaxf(o0.x - (acc[mf][nf][0] + bv.x), 0.f);
                        OS[b0i + 2] = fmaxf(o0.y - (acc[mf][nf][1] + bv.y), 0.f);
                        OS[b1i] = fmaxf(o1.x - (acc[mf][nf][2] + bv.x), 0.f);
                        OS[b1i + 2] = fmaxf(o1.y - (acc[mf][nf][3] + bv.y), 0.f);
                    }
            }
            __syncthreads();
#pragma unroll
            for (int p = 0; p < 6; p++) {
                int idx = tid + (p << 8);
                int bnL = idx >> 6, off = idx & 63;
                *reinterpret_cast<float4*>(
                    outp + (size_t)(bn0 + pass * 24 + bnL) * (2 * CONCATN) + n0 * 2 + off * 4) =
                    *reinterpret_cast<const float4*>(&OS[bnL * 256 + off * 4]);
            }
            __syncthreads();
        }
    }
}

// ---------------- launcher ----------------
extern "C" void kernel_launch(void* const* d_in, const int* in_sizes, int n_in,
                              void* d_out, int out_size) {
    const float* history = (const float*)d_in[0];
    const float* tod     = (const float*)d_in[1];
    const float* emb     = (const float*)d_in[2];
    const float* tg1_w = (const float*)d_in[3];
    const float* tg1_b = (const float*)d_in[4];
    const float* tg2_w = (const float*)d_in[5];
    const float* tg2_b = (const float*)d_in[6];
    const float* tg3_w = (const float*)d_in[7];
    const float* tg3_b = (const float*)d_in[8];
    const float* fc0_w = (const float*)d_in[9];
    const float* fc0_b = (const float*)d_in[10];
    const float* fc_w  = (const float*)d_in[11];
    const float* fc_b  = (const float*)d_in[12];
    const float* fore_w = (const float*)d_in[13];
    const float* fore_b = (const float*)d_in[14];
    const float* back_w = (const float*)d_in[15];
    const float* back_b = (const float*)d_in[16];
    float* out = (float*)d_out;

    float *pH2, *pF;
    __half *pX, *pW0t, *pWfct, *pWbt;
    cudaGetSymbolAddress((void**)&pX, g_Xh);
    cudaGetSymbolAddress((void**)&pH2, g_H2);
    cudaGetSymbolAddress((void**)&pF, g_F);
    cudaGetSymbolAddress((void**)&pW0t, g_W0t);
    cudaGetSymbolAddress((void**)&pWfct, g_Wfct);
    cudaGetSymbolAddress((void**)&pWbt, g_Wbt);

    cudaFuncSetAttribute(block_mlp_kernel, cudaFuncAttributeMaxDynamicSharedMemorySize, BLK_SMEM);
    cudaFuncSetAttribute(gemm_back_kernel<1>, cudaFuncAttributeMaxDynamicSharedMemorySize, BACK_SMEM);
    cudaFuncSetAttribute(gemm_back_kernel<3>, cudaFuncAttributeMaxDynamicSharedMemorySize, BACK_SMEM);

    timegate_kernel<<<BNCNT / TG_NB, 256>>>(history, tod, emb, tg1_w, tg1_b, tg2_w, tg2_b, tg3_w, tg3_b);
    dp_kernel<<<(NN * NN + 255) / 256, 256>>>(emb);
    transpose_all_kernel<<<2016, dim3(32, 8)>>>(fc0_w, fc_w, back_w);
    build_hist_kernel<<<dim3(BB, 23), 256>>>(emb);

    float* outF = out + (size_t)MROWS * CONCATN;
    for (int i = 0; i < 3; i++) {
        block_mlp_kernel<<<GMX, 256, BLK_SMEM>>>(
            pX, pW0t + (size_t)i * HH * CONCATN, fc0_b + i * HH,
            pWfct + (size_t)i * 2 * HH * HH, fc_b + i * 2 * HH,
            fore_w + (size_t)i * HH * HORZ, fore_b + i * HORZ,
            pH2, pF, outF, i);
        if (i < 2)
            gemm_back_kernel<1><<<dim3(GMX, CONCATN / G_BN), 256, BACK_SMEM>>>(
                pH2, pWbt + (size_t)i * CONCATN * HH, back_b + (size_t)i * CONCATN, pX, nullptr);
        else
            gemm_back_kernel<3><<<dim3(GMX, CONCATN / G_BN), 256, BACK_SMEM>>>(
                pH2, pWbt + (size_t)i * CONCATN * HH, back_b + (size_t)i * CONCATN, pX, out);
    }
}

// round 17
// speedup vs baseline: 1.0433x; 1.0433x over previous
#include <cuda_runtime.h>
#include <cuda_fp16.h>
#include <math.h>
#include <stdint.h>

#define NN 207
#define BB 32
#define TT 12
#define CC 2
#define HORZ 12
#define DID 64
#define HH 128
#define CONCATN 2560          // DID + TT + NN*TT
#define MROWS (BB*NN*CC)      // 13248 = 138*96
#define MPAD 13248
#define BNCNT (BB*NN)         // 6624
#define GMX 138
#define EPSILON_V 10.0f
#define EPS_V 1e-8f
#define HIN_B (CC*TT*NN)      // 4968, per-batch h_in block, layout [c][t][src]
#define NGRP 9                // nodes per build_hist CTA (23*9 = 207)

// ---------------- scratch (device globals; no allocation) ----------------
__device__ __half g_Xh[(size_t)MPAD * CONCATN]; // fp16 X (~68MB)
__device__ float g_H2[MPAD * HH];               // fc2 output (back-GEMM input, fp32)
__device__ float g_F[MPAD * HORZ];
__device__ float g_hin[BB * HIN_B];             // [b][c][t][src]
__device__ float g_level[BNCNT * CC];
__device__ float g_tgf[BNCNT * HORZ];
__device__ float g_dp[NN * NN];
// transposed weights (N x K, K-major), fp16
__device__ __half g_W0t[3 * HH * CONCATN];
__device__ __half g_Wfct[3 * 2 * HH * HH];
__device__ __half g_Wbt[3 * CONCATN * HH];

// ---------------- helpers ----------------
__device__ __forceinline__ uint32_t smem_u32(const void* p) {
    uint32_t a;
    asm("{ .reg .u64 t; cvta.to.shared.u64 t, %1; cvt.u32.u64 %0, t; }" : "=r"(a) : "l"(p));
    return a;
}
__device__ __forceinline__ uint32_t pack_f16x2(float lo, float hi) {
    uint32_t r;
    asm("cvt.rn.f16x2.f32 %0, %1, %2;" : "=r"(r) : "f"(hi), "f"(lo));
    return r;
}
__device__ __forceinline__ __half2 h2_from(float a, float b) {
    return __floats2half2_rn(a, b);
}
#define CP_ASYNC16(s, g) asm volatile("cp.async.cg.shared.global [%0], [%1], 16;" :: "r"(s), "l"(g))
#define CP_COMMIT()      asm volatile("cp.async.commit_group;" ::: "memory")
#define CP_WAIT(n)       asm volatile("cp.async.wait_group %0;" :: "n"(n) : "memory")

__device__ __forceinline__ void mma_f16(float* d, const uint32_t* a, const uint32_t* b) {
    asm volatile("mma.sync.aligned.m16n8k16.row.col.f32.f16.f16.f32 "
                 "{%0,%1,%2,%3}, {%4,%5,%6,%7}, {%8,%9}, {%0,%1,%2,%3};"
                 : "+f"(d[0]), "+f"(d[1]), "+f"(d[2]), "+f"(d[3])
                 : "r"(a[0]), "r"(a[1]), "r"(a[2]), "r"(a[3]), "r"(b[0]), "r"(b[1]));
}

// ---------------- time gates + h_in + level (round-15 version) ----------------
__global__ void timegate_kernel(const float* __restrict__ hist,
                                const float* __restrict__ tod,
                                const float* __restrict__ emb,
                                const float* __restrict__ w1, const float* __restrict__ b1,
                                const float* __restrict__ w2, const float* __restrict__ b2,
                                const float* __restrict__ w3, const float* __restrict__ b3) {
    int bn = blockIdx.x;
    int b = bn / NN, n = bn % NN;
    __shared__ float sin_[DID + TT];
    __shared__ float stg[HH];
    __shared__ float stgb[TT];
    __shared__ float shin[TT * CC];
    int t = threadIdx.x;  // 128
    if (t < DID) sin_[t] = emb[n * DID + t];
    else if (t < DID + TT) sin_[t] = tod[bn * TT + (t - DID)];
    __syncthreads();
    float acc = b1[t];
#pragma unroll 4
    for (int i = 0; i < DID + TT; i++) acc += sin_[i] * w1[i * HH + t];
    stg[t] = fmaxf(acc, 0.f);
    __syncthreads();
    if (t < HORZ) {
        float a2 = b2[t], a3 = b3[t];
#pragma unroll 8
        for (int h = 0; h < HH; h++) {
            float v = stg[h];
            a2 += v * w2[h * HORZ + t];
            a3 += v * w3[h * TT + t];
        }
        g_tgf[bn * HORZ + t] = a2;
        stgb[t] = a3;
    }
    __syncthreads();
    if (t < TT * CC) {
        int tt = t >> 1, c = t & 1;
        float hv = hist[((size_t)bn * TT + tt) * CC + c] / (1.f + stgb[tt]);
        shin[t] = hv;
        g_hin[b * HIN_B + (c * TT + tt) * NN + n] = hv;
    }
    __syncthreads();
    if (t < CC) {
        float mx = -1e30f;
#pragma unroll
        for (int tt = 0; tt < TT; tt++) mx = fmaxf(mx, shin[tt * CC + t]);
        g_level[bn * CC + t] = mx;
    }
}

// ---------------- pairwise affinities ----------------
__global__ void dp_kernel(const float* __restrict__ emb) {
    int idx = blockIdx.x * blockDim.x + threadIdx.x;
    if (idx >= NN * NN) return;
    int i = idx / NN, j = idx % NN;
    float s = 0.f;
#pragma unroll 8
    for (int k = 0; k < DID; k++) s += emb[i * DID + k] * emb[j * DID + k];
    g_dp[idx] = expf(EPSILON_V * s);
}

// ---------------- build X: one CTA per (batch, 9-node group), dp double-buffered ----------------
__global__ void build_hist_kernel(const float* __restrict__ emb) {
    int b = blockIdx.x;       // 0..31
    int grp = blockIdx.y;     // 0..22
    __shared__ __align__(16) __half sout[CC * CONCATN];  // 10240 B
    __shared__ float sh[HIN_B];              // [c][t][src], 19872 B
    __shared__ float sdp[2][NN];
    __shared__ float slvl[2][CC];
    int tid = threadIdx.x;                   // 256

    const float4* hin4 = reinterpret_cast<const float4*>(&g_hin[b * HIN_B]);
    float4* sh4 = reinterpret_cast<float4*>(sh);
    for (int i = tid; i < HIN_B / 4; i += 256) sh4[i] = hin4[i];
    {
        int n0 = grp * NGRP;
        if (tid < NN) sdp[0][tid] = g_dp[n0 * NN + tid];
        if (tid >= 254) slvl[0][tid - 254] = g_level[(b * NN + n0) * CC + (tid - 254)];
    }
    __syncthreads();

    for (int nn = 0; nn < NGRP; nn++) {
        int cur = nn & 1;
        int n = grp * NGRP + nn;
        int bn = b * NN + n;
        if (nn + 1 < NGRP) {
            int n1 = n + 1;
            if (tid < NN) sdp[cur ^ 1][tid] = g_dp[n1 * NN + tid];
            if (tid >= 254) slvl[cur ^ 1][tid - 254] = g_level[(bn + 1) * CC + (tid - 254)];
        }
        float lv[2] = {slvl[cur][0], slvl[cur][1]};
        float rl[2] = {1.f / (lv[0] + EPS_V), 1.f / (lv[1] + EPS_V)};

        for (int pair = tid; pair < 2 * NN; pair += 256) {
            int c = (pair >= NN) ? 1 : 0;
            int src = pair - NN * c;
            float d = sdp[cur][src];
            float l = lv[c], r = rl[c];
            float v[12];
#pragma unroll
            for (int t = 0; t < 12; t++) {
                float a = sh[(c * TT + t) * NN + src] * d;
                v[t] = fmaxf((a - l) * r, 0.f);
            }
            __half2* dst = reinterpret_cast<__half2*>(&sout[c * CONCATN + 12 + src * 12]);
#pragma unroll
            for (int q = 0; q < 6; q++) dst[q] = h2_from(v[2 * q], v[2 * q + 1]);
        }
        if (tid < 24) {
            int c = tid >= 12 ? 1 : 0;
            int t = tid - 12 * c;
            sout[c * CONCATN + t] = __float2half_rn(sh[(c * TT + t) * NN + n] * rl[c]);
        }
        if (tid < 128) {
            int c = tid >> 6, d = tid & 63;
            sout[c * CONCATN + (TT + NN * TT) + d] = __float2half_rn(emb[n * DID + d]);
        }
        __syncthreads();
        uint4* xb4 = reinterpret_cast<uint4*>(&g_Xh[(size_t)bn * CC * CONCATN]);
        const uint4* s4 = reinterpret_cast<const uint4*>(sout);
#pragma unroll
        for (int p = 0; p < 3; p++) {
            int i = tid + (p << 8);
            if (i < 640) xb4[i] = s4[i];
        }
        __syncthreads();
    }
}

// ---------------- batched weight transpose -> fp16 (N x K) ----------------
__global__ void transpose_all_kernel(const float* __restrict__ fc0_w,
                                     const float* __restrict__ fc_w,
                                     const float* __restrict__ back_w) {
    __shared__ float t[32][33];
    int idx = blockIdx.x;
    int blk = idx / 672;
    int r = idx % 672;
    const float* in;
    __half* out;
    int K, N, kb, nb;
    if (r < 320) {
        in = fc0_w + (size_t)blk * CONCATN * HH;
        out = g_W0t + (size_t)blk * HH * CONCATN;
        K = CONCATN; N = HH; kb = (r % 80) * 32; nb = (r / 80) * 32;
    } else if (r < 336) {
        r -= 320;
        in = fc_w + ((size_t)blk * 2 + 0) * HH * HH;
        out = g_Wfct + ((size_t)blk * 2 + 0) * HH * HH;
        K = HH; N = HH; kb = (r % 4) * 32; nb = (r / 4) * 32;
    } else if (r < 352) {
        r -= 336;
        in = fc_w + ((size_t)blk * 2 + 1) * HH * HH;
        out = g_Wfct + ((size_t)blk * 2 + 1) * HH * HH;
        K = HH; N = HH; kb = (r % 4) * 32; nb = (r / 4) * 32;
    } else {
        r -= 352;
        in = back_w + (size_t)blk * HH * CONCATN;
        out = g_Wbt + (size_t)blk * CONCATN * HH;
        K = HH; N = CONCATN; kb = (r % 4) * 32; nb = (r / 4) * 32;
    }
    int x = threadIdx.x, y = threadIdx.y;  // 32 x 8
#pragma unroll
    for (int rr = 0; rr < 32; rr += 8)
        t[y + rr][x] = in[(size_t)(kb + y + rr) * N + nb + x];
    __syncthreads();
#pragma unroll
    for (int rr = 0; rr < 32; rr += 8)
        out[(size_t)(nb + y + rr) * K + kb + x] = __float2half_rn(t[x][y + rr]);
}

// ---------------- shared tiling constants ----------------
#define G_BM 96
#define G_BN 128
#define SB_STR 40                        // halves per B smem row
#define B_STG_B (G_BN * SB_STR * 2)      // 10240 bytes

// ===== block_mlp: fp16 A (X), 4-stage fc0 pipeline =====
#define MB_ASTG (G_BM * 40 * 2)          // 7680 bytes
#define MB_STG (MB_ASTG + B_STG_B)       // 17920
#define NSTAGE 4
#define WF_OFF (NSTAGE * MB_STG)         // 71680
#define WFMAT 40960
#define WFCH 10240
#define HSTR 136
#define H_BYTES (G_BM * HSTR * 2)        // 26112
#define H0_OFF (WF_OFF + 2 * WFMAT)      // 153600
#define H1_OFF (H0_OFF + H_BYTES)        // 179712
#define FW_OFF (H1_OFF + H_BYTES)        // 205824
#define BLK_SMEM (FW_OFF + 6144)         // 211968

// ===== back gemm: fp32 A (H2), 2-stage, X staging =====
#define BA_STR 40
#define BA_STG_B (G_BM * BA_STR * 4)     // 15360
#define BSTG_B (BA_STG_B + B_STG_B)      // 25600
#define XS_OFF (2 * BSTG_B)              // 51200
#define XS_BYTES (G_BM * HSTR * 2)       // 26112
#define OS_OFF (XS_OFF + XS_BYTES)       // 77312
#define OS_BYTES 24576
#define BACK_SMEM (OS_OFF + OS_BYTES)    // 101888

// ---------------- fused block kernel: fc0 -> fc1 -> fc2 -> fore ----------------
__global__ void __launch_bounds__(256) block_mlp_kernel(
        const __half* __restrict__ Xh, const __half* __restrict__ W0t,
        const float* __restrict__ b0,
        const __half* __restrict__ Wf, const float* __restrict__ fcb,
        const float* __restrict__ fore_w, const float* __restrict__ fore_b,
        float* __restrict__ H2out, float* __restrict__ Fbuf,
        float* __restrict__ outF, int blk) {
    extern __shared__ char smc[];
    const int tid = threadIdx.x;
    const int wid = tid >> 5, lid = tid & 31;
    const int wm = wid >> 2, wn = wid & 3;
    const int g = lid >> 2, t = lid & 3;
    const int m0 = blockIdx.x * G_BM;

    const __half* gA = Xh + (size_t)m0 * CONCATN;
    const __half* gB = W0t;
    const uint32_t sm_u = smem_u32(smc);
    const int nch = CONCATN >> 5;              // 80

    // preload Wf1/Wf2 + fore_w
#pragma unroll
    for (int p = 0; p < 16; p++) {
        int idx = tid + (p << 8);
        int w = idx >> 11;
        int rem = idx & 2047;
        int ch = rem >> 9;
        int r2 = rem & 511;
        int row = r2 >> 2;
        int kh = (r2 & 3) << 3;
        CP_ASYNC16(sm_u + WF_OFF + w * WFMAT + ch * WFCH + (row * 40 + kh) * 2,
                   Wf + (size_t)w * HH * HH + row * HH + ch * 32 + kh);
    }
#pragma unroll
    for (int p = 0; p < 2; p++) {
        int idx = tid + (p << 8);
        if (idx < 384)
            CP_ASYNC16(sm_u + FW_OFF + idx * 16, fore_w + idx * 4);
    }
    CP_COMMIT();

    auto load_tiles = [&](int k0, int st) {
        uint32_t base = sm_u + st * MB_STG;
        {
            int idx = tid;
            int row = idx >> 2, kh = (idx & 3) << 3;
            CP_ASYNC16(base + (row * 40 + kh) * 2, gA + (size_t)row * CONCATN + k0 + kh);
        }
        if (tid < 128) {
            int idx = tid + 256;
            int row = idx >> 2, kh = (idx & 3) << 3;
            CP_ASYNC16(base + (row * 40 + kh) * 2, gA + (size_t)row * CONCATN + k0 + kh);
        }
        uint32_t baseB = base + MB_ASTG;
#pragma unroll
        for (int p = 0; p < 2; p++) {
            int idx = tid + (p << 8);
            int row = idx >> 2, kh = (idx & 3) << 3;
            CP_ASYNC16(baseB + (row * SB_STR + kh) * 2, gB + (size_t)row * CONCATN + k0 + kh);
        }
        CP_COMMIT();
    };

    float acc[3][4][4];
#pragma unroll
    for (int mf = 0; mf < 3; mf++)
#pragma unroll
        for (int nf = 0; nf < 4; nf++)
#pragma unroll
            for (int q = 0; q < 4; q++) acc[mf][nf][q] = 0.f;

    // ========== stage 1: fc0 (K=2560, 4-stage, single barrier per chunk) ==========
    load_tiles(0, 0);
    load_tiles(32, 1);

    for (int ch = 0; ch < nch; ch++) {
        int st = ch & 3;
        if (ch + 2 < nch) {
            load_tiles((ch + 2) << 5, (ch + 2) & 3);
            CP_WAIT(2);
        } else if (ch + 1 < nch) {
            CP_WAIT(1);
        } else {
            CP_WAIT(0);
        }
        __syncthreads();

        const uint32_t* sA = reinterpret_cast<const uint32_t*>(smc + st * MB_STG);
        const uint32_t* sB = reinterpret_cast<const uint32_t*>(smc + st * MB_STG + MB_ASTG);
#pragma unroll
        for (int ks = 0; ks < 2; ks++) {
            uint32_t af[3][4];
#pragma unroll
            for (int mf = 0; mf < 3; mf++) {
                int r = wm * 48 + mf * 16 + g;
                int base = r * 20 + ks * 8 + t;
                af[mf][0] = sA[base];
                af[mf][1] = sA[base + 160];
                af[mf][2] = sA[base + 4];
                af[mf][3] = sA[base + 164];
            }
            uint32_t bf[4][2];
#pragma unroll
            for (int nf = 0; nf < 4; nf++) {
                int n = wn * 32 + nf * 8 + g;
                int base = n * 20 + ks * 8 + t;
                bf[nf][0] = sB[base];
                bf[nf][1] = sB[base + 4];
            }
#pragma unroll
            for (int mf = 0; mf < 3; mf++)
#pragma unroll
                for (int nf = 0; nf < 4; nf++)
                    mma_f16(acc[mf][nf], af[mf], bf[nf]);
        }
        // no trailing barrier: with 4 stages, the stage written at iteration
        // ch+1 (stage (ch+3)&3) was last computed at iteration ch-1, and the
        // leading barrier of iteration ch proves all warps finished it.
    }
    __syncthreads();

    __half* sH0h = reinterpret_cast<__half*>(smc + H0_OFF);
    __half* sH1h = reinterpret_cast<__half*>(smc + H1_OFF);
#pragma unroll
    for (int mf = 0; mf < 3; mf++)
#pragma unroll
        for (int nf = 0; nf < 4; nf++) {
            int row = wm * 48 + mf * 16 + g;
            int col = wn * 32 + nf * 8 + 2 * t;
            float2 bv = *reinterpret_cast<const float2*>(&b0[col]);
            *reinterpret_cast<__half2*>(&sH0h[row * HSTR + col]) =
                h2_from(fmaxf(acc[mf][nf][0] + bv.x, 0.f), fmaxf(acc[mf][nf][1] + bv.y, 0.f));
            *reinterpret_cast<__half2*>(&sH0h[(row + 8) * HSTR + col]) =
                h2_from(fmaxf(acc[mf][nf][2] + bv.x, 0.f), fmaxf(acc[mf][nf][3] + bv.y, 0.f));
        }
    __syncthreads();

    // ========== stages 2/3: fc1, fc2 from smem ==========
#pragma unroll 1
    for (int stage = 0; stage < 2; stage++) {
        const uint32_t* sAH = reinterpret_cast<const uint32_t*>(stage == 0 ? sH0h : sH1h);
        const float* bias = fcb + stage * HH;
#pragma unroll
        for (int mf = 0; mf < 3; mf++)
#pragma unroll
            for (int nf = 0; nf < 4; nf++)
#pragma unroll
                for (int q = 0; q < 4; q++) acc[mf][nf][q] = 0.f;

#pragma unroll
        for (int ch = 0; ch < 4; ch++) {
            const uint32_t* W32 = reinterpret_cast<const uint32_t*>(
                smc + WF_OFF + stage * WFMAT + ch * WFCH);
#pragma unroll
            for (int ks = 0; ks < 2; ks++) {
                uint32_t af[3][4];
#pragma unroll
                for (int mf = 0; mf < 3; mf++) {
                    int r = wm * 48 + mf * 16 + g;
                    int base = r * (HSTR / 2) + ch * 16 + ks * 8 + t;
                    af[mf][0] = sAH[base];
                    af[mf][1] = sAH[base + 8 * (HSTR / 2)];
                    af[mf][2] = sAH[base + 4];
                    af[mf][3] = sAH[base + 8 * (HSTR / 2) + 4];
                }
                uint32_t bf[4][2];
#pragma unroll
                for (int nf = 0; nf < 4; nf++) {
                    int n = wn * 32 + nf * 8 + g;
                    int base = n * (SB_STR / 2) + ks * 8 + t;
                    bf[nf][0] = W32[base];
                    bf[nf][1] = W32[base + 4];
                }
#pragma unroll
                for (int mf = 0; mf < 3; mf++)
#pragma unroll
                    for (int nf = 0; nf < 4; nf++)
                        mma_f16(acc[mf][nf], af[mf], bf[nf]);
            }
        }

        if (stage == 0) {
#pragma unroll
            for (int mf = 0; mf < 3; mf++)
#pragma unroll
                for (int nf = 0; nf < 4; nf++) {
                    int row = wm * 48 + mf * 16 + g;
                    int col = wn * 32 + nf * 8 + 2 * t;
                    float2 bv = *reinterpret_cast<const float2*>(&bias[col]);
                    *reinterpret_cast<__half2*>(&sH1h[row * HSTR + col]) =
                        h2_from(fmaxf(acc[mf][nf][0] + bv.x, 0.f), fmaxf(acc[mf][nf][1] + bv.y, 0.f));
                    *reinterpret_cast<__half2*>(&sH1h[(row + 8) * HSTR + col]) =
                        h2_from(fmaxf(acc[mf][nf][2] + bv.x, 0.f), fmaxf(acc[mf][nf][3] + bv.y, 0.f));
                }
        } else {
#pragma unroll
            for (int mf = 0; mf < 3; mf++)
#pragma unroll
                for (int nf = 0; nf < 4; nf++) {
                    int row = wm * 48 + mf * 16 + g;
                    int col = wn * 32 + nf * 8 + 2 * t;
                    float2 bv = *reinterpret_cast<const float2*>(&bias[col]);
                    float v0 = fmaxf(acc[mf][nf][0] + bv.x, 0.f);
                    float v1 = fmaxf(acc[mf][nf][1] + bv.y, 0.f);
                    float v2 = fmaxf(acc[mf][nf][2] + bv.x, 0.f);
                    float v3 = fmaxf(acc[mf][nf][3] + bv.y, 0.f);
                    float2 r0; r0.x = v0; r0.y = v1;
                    float2 r1; r1.x = v2; r1.y = v3;
                    *reinterpret_cast<float2*>(&H2out[(size_t)(m0 + row) * HH + col]) = r0;
                    *reinterpret_cast<float2*>(&H2out[(size_t)(m0 + row + 8) * HH + col]) = r1;
                    *reinterpret_cast<__half2*>(&sH0h[row * HSTR + col]) = h2_from(v0, v1);
                    *reinterpret_cast<__half2*>(&sH0h[(row + 8) * HSTR + col]) = h2_from(v2, v3);
                }
        }
        __syncthreads();
    }

    // ========== stage 4: fore (SIMT, N=12) ==========
    const float* sFW = reinterpret_cast<const float*>(smc + FW_OFF);
    for (int o = tid; o < G_BM * HORZ; o += 256) {
        int row = o / HORZ, col = o - row * HORZ;
        float a = __ldg(&fore_b[col]);
#pragma unroll 16
        for (int k = 0; k < HH; k++)
            a += __half2float(sH0h[row * HSTR + k]) * sFW[k * HORZ + col];
        int gr = m0 + row;
        if (blk == 0) {
            Fbuf[gr * HORZ + col] = a;
        } else if (blk == 1) {
            Fbuf[gr * HORZ + col] += a;
        } else {
            float tot = Fbuf[gr * HORZ + col] + a;
            int bn = gr >> 1, c = gr & 1;
            tot *= g_level[bn * CC + c] * (1.f + g_tgf[bn * HORZ + col]);
            outF[bn * (HORZ * CC) + col * CC + c] = tot;
        }
    }
}

// ---------------- back GEMM (fp32 A=H2, fp16 X, staged epilogues) ----------------
template <int EPI>
__global__ void __launch_bounds__(256) gemm_back_kernel(
        const float* __restrict__ A, const __half* __restrict__ Bt,
        const float* __restrict__ bias, __half* __restrict__ Xh,
        float* __restrict__ outp) {
    extern __shared__ char smc[];
    const int tid = threadIdx.x;
    const int wid = tid >> 5, lid = tid & 31;
    const int wm = wid >> 2, wn = wid & 3;
    const int g = lid >> 2, t = lid & 3;
    const int m0 = blockIdx.x * G_BM, n0 = blockIdx.y * G_BN;
    const int K = HH;
    const int nch = 4;

    const float* gA = A + (size_t)m0 * K;
    const __half* gB = Bt + (size_t)n0 * K;
    __half* gX = Xh + (size_t)m0 * CONCATN + n0;
    const uint32_t sm_u = smem_u32(smc);

    auto issue_tile = [&](int k0, int st) {
        uint32_t base = sm_u + st * BSTG_B;
#pragma unroll
        for (int p = 0; p < 3; p++) {
            int idx = tid + (p << 8);
            int row = idx >> 3, kc = (idx & 7) << 2;
            CP_ASYNC16(base + (row * BA_STR + kc) * 4, gA + (size_t)row * K + k0 + kc);
        }
        uint32_t baseB = base + BA_STG_B;
#pragma unroll
        for (int p = 0; p < 2; p++) {
            int idx = tid + (p << 8);
            int row = idx >> 2, kh = (idx & 3) << 3;
            CP_ASYNC16(baseB + (row * SB_STR + kh) * 2, gB + (size_t)row * K + k0 + kh);
        }
    };
#pragma unroll
    for (int p = 0; p < 6; p++) {
        int idx = tid + (p << 8);
        int row = idx >> 4, seg = idx & 15;
        CP_ASYNC16(sm_u + XS_OFF + row * (HSTR * 2) + seg * 16,
                   gX + (size_t)row * CONCATN + seg * 8);
    }
    issue_tile(0, 0);
    CP_COMMIT();
    issue_tile(32, 1);
    CP_COMMIT();

    float acc[3][4][4];
#pragma unroll
    for (int mf = 0; mf < 3; mf++)
#pragma unroll
        for (int nf = 0; nf < 4; nf++)
#pragma unroll
            for (int q = 0; q < 4; q++) acc[mf][nf][q] = 0.f;

    for (int ch = 0; ch < nch; ch++) {
        int st = ch & 1;
        if (ch + 1 < nch) CP_WAIT(1);
        else CP_WAIT(0);
        __syncthreads();

        const float* sA = reinterpret_cast<const float*>(smc + st * BSTG_B);
        const uint32_t* sB = reinterpret_cast<const uint32_t*>(smc + st * BSTG_B + BA_STG_B);
#pragma unroll
        for (int ks = 0; ks < 2; ks++) {
            int kb = ks << 4;
            uint32_t af[3][4];
#pragma unroll
            for (int mf = 0; mf < 3; mf++) {
                int r = wm * 48 + mf * 16 + g;
                float2 f0 = *reinterpret_cast<const float2*>(&sA[r * BA_STR + kb + 2 * t]);
                float2 f1 = *reinterpret_cast<const float2*>(&sA[(r + 8) * BA_STR + kb + 2 * t]);
                float2 f2 = *reinterpret_cast<const float2*>(&sA[r * BA_STR + kb + 8 + 2 * t]);
                float2 f3 = *reinterpret_cast<const float2*>(&sA[(r + 8) * BA_STR + kb + 8 + 2 * t]);
                af[mf][0] = pack_f16x2(f0.x, f0.y);
                af[mf][1] = pack_f16x2(f1.x, f1.y);
                af[mf][2] = pack_f16x2(f2.x, f2.y);
                af[mf][3] = pack_f16x2(f3.x, f3.y);
            }
            uint32_t bf[4][2];
#pragma unroll
            for (int nf = 0; nf < 4; nf++) {
                int n = wn * 32 + nf * 8 + g;
                int base = n * (SB_STR / 2) + ks * 8 + t;
                bf[nf][0] = sB[base];
                bf[nf][1] = sB[base + 4];
            }
#pragma unroll
            for (int mf = 0; mf < 3; mf++)
#pragma unroll
                for (int nf = 0; nf < 4; nf++)
                    mma_f16(acc[mf][nf], af[mf], bf[nf]);
        }
        __syncthreads();
        if (ch + 2 < nch) {
            issue_tile((ch + 2) << 5, st);
            CP_COMMIT();
        }
    }

    __half* XS = reinterpret_cast<__half*>(smc + XS_OFF);
    if (EPI == 1) {
#pragma unroll
        for (int mf = 0; mf < 3; mf++)
#pragma unroll
            for (int nf = 0; nf < 4; nf++) {
                int row = wm * 48 + mf * 16 + g;
                int col = wn * 32 + nf * 8 + 2 * t;
                float2 bv = *reinterpret_cast<const float2*>(&bias[n0 + col]);
                float2 o0 = __half22float2(*reinterpret_cast<const __half2*>(&XS[row * HSTR + col]));
                float2 o1 = __half22float2(*reinterpret_cast<const __half2*>(&XS[(row + 8) * HSTR + col]));
                *reinterpret_cast<__half2*>(&XS[row * HSTR + col]) =
                    h2_from(fmaxf(o0.x - (acc[mf][nf][0] + bv.x), 0.f),
                            fmaxf(o0.y - (acc[mf][nf][1] + bv.y), 0.f));
                *reinterpret_cast<__half2*>(&XS[(row + 8) * HSTR + col]) =
                    h2_from(fmaxf(o1.x - (acc[mf][nf][2] + bv.x), 0.f),
                            fmaxf(o1.y - (acc[mf][nf][3] + bv.y), 0.f));
            }
        __syncthreads();
#pragma unroll
        for (int p = 0; p < 6; p++) {
            int idx = tid + (p << 8);
            int row = idx >> 4, seg = idx & 15;
            *reinterpret_cast<uint4*>(gX + (size_t)row * CONCATN + seg * 8) =
                *reinterpret_cast<const uint4*>(&XS[row * HSTR + seg * 8]);
        }
    } else {
        float* OS = reinterpret_cast<float*>(smc + OS_OFF);
        const int bn0 = m0 >> 1;
#pragma unroll 1
        for (int pass = 0; pass < 2; pass++) {
            if (wm == pass) {
#pragma unroll
                for (int mf = 0; mf < 3; mf++)
#pragma unroll
                    for (int nf = 0; nf < 4; nf++) {
                        int row = wm * 48 + mf * 16 + g;
                        int col = wn * 32 + nf * 8 + 2 * t;
                        float2 bv = *reinterpret_cast<const float2*>(&bias[n0 + col]);
                        float2 o0 = __half22float2(*reinterpret_cast<const __half2*>(&XS[row * HSTR + col]));
                        float2 o1 = __half22float2(*reinterpret_cast<const __half2*>(&XS[(row + 8) * HSTR + col]));
                        int b0i = ((row >> 1) - pass * 24) * 256 + col * 2 + (row & 1);
                        int b1i = (((row + 8) >> 1) - pass * 24) * 256 + col * 2 + (row & 1);
                        OS[b0i] = fmaxf(o0.x - (acc[mf][nf][0] + bv.x), 0.f);
                        OS[b0i + 2] = fmaxf(o0.y - (acc[mf][nf][1] + bv.y), 0.f);
                        OS[b1i] = fmaxf(o1.x - (acc[mf][nf][2] + bv.x), 0.f);
                        OS[b1i + 2] = fmaxf(o1.y - (acc[mf][nf][3] + bv.y), 0.f);
                    }
            }
            __syncthreads();
#pragma unroll
            for (int p = 0; p < 6; p++) {
                int idx = tid + (p << 8);
                int bnL = idx >> 6, off = idx & 63;
                *reinterpret_cast<float4*>(
                    outp + (size_t)(bn0 + pass * 24 + bnL) * (2 * CONCATN) + n0 * 2 + off * 4) =
                    *reinterpret_cast<const float4*>(&OS[bnL * 256 + off * 4]);
            }
            __syncthreads();
        }
    }
}

// ---------------- launcher ----------------
extern "C" void kernel_launch(void* const* d_in, const int* in_sizes, int n_in,
                              void* d_out, int out_size) {
    const float* history = (const float*)d_in[0];
    const float* tod     = (const float*)d_in[1];
    const float* emb     = (const float*)d_in[2];
    const float* tg1_w = (const float*)d_in[3];
    const float* tg1_b = (const float*)d_in[4];
    const float* tg2_w = (const float*)d_in[5];
    const float* tg2_b = (const float*)d_in[6];
    const float* tg3_w = (const float*)d_in[7];
    const float* tg3_b = (const float*)d_in[8];
    const float* fc0_w = (const float*)d_in[9];
    const float* fc0_b = (const float*)d_in[10];
    const float* fc_w  = (const float*)d_in[11];
    const float* fc_b  = (const float*)d_in[12];
    const float* fore_w = (const float*)d_in[13];
    const float* fore_b = (const float*)d_in[14];
    const float* back_w = (const float*)d_in[15];
    const float* back_b = (const float*)d_in[16];
    float* out = (float*)d_out;

    float *pH2, *pF;
    __half *pX, *pW0t, *pWfct, *pWbt;
    cudaGetSymbolAddress((void**)&pX, g_Xh);
    cudaGetSymbolAddress((void**)&pH2, g_H2);
    cudaGetSymbolAddress((void**)&pF, g_F);
    cudaGetSymbolAddress((void**)&pW0t, g_W0t);
    cudaGetSymbolAddress((void**)&pWfct, g_Wfct);
    cudaGetSymbolAddress((void**)&pWbt, g_Wbt);

    cudaFuncSetAttribute(block_mlp_kernel, cudaFuncAttributeMaxDynamicSharedMemorySize, BLK_SMEM);
    cudaFuncSetAttribute(gemm_back_kernel<1>, cudaFuncAttributeMaxDynamicSharedMemorySize, BACK_SMEM);
    cudaFuncSetAttribute(gemm_back_kernel<3>, cudaFuncAttributeMaxDynamicSharedMemorySize, BACK_SMEM);

    timegate_kernel<<<BNCNT, 128>>>(history, tod, emb, tg1_w, tg1_b, tg2_w, tg2_b, tg3_w, tg3_b);
    dp_kernel<<<(NN * NN + 255) / 256, 256>>>(emb);
    transpose_all_kernel<<<2016, dim3(32, 8)>>>(fc0_w, fc_w, back_w);
    build_hist_kernel<<<dim3(BB, 23), 256>>>(emb);

    float* outF = out + (size_t)MROWS * CONCATN;
    for (int i = 0; i < 3; i++) {
        block_mlp_kernel<<<GMX, 256, BLK_SMEM>>>(
            pX, pW0t + (size_t)i * HH * CONCATN, fc0_b + i * HH,
            pWfct + (size_t)i * 2 * HH * HH, fc_b + i * 2 * HH,
            fore_w + (size_t)i * HH * HORZ, fore_b + i * HORZ,
            pH2, pF, outF, i);
        if (i < 2)
            gemm_back_kernel<1><<<dim3(GMX, CONCATN / G_BN), 256, BACK_SMEM>>>(
                pH2, pWbt + (size_t)i * CONCATN * HH, back_b + (size_t)i * CONCATN, pX, nullptr);
        else
            gemm_back_kernel<3><<<dim3(GMX, CONCATN / G_BN), 256, BACK_SMEM>>>(
                pH2, pWbt + (size_t)i * CONCATN * HH, back_b + (size_t)i * CONCATN, pX, out);
    }
}